// round 4
// baseline (speedup 1.0000x reference)
#include <cuda_runtime.h>
#include <cstdint>

// Problem constants (fixed shapes for this problem instance)
#define DD     192          // projection dim
#define MM     128          // memory bank size
#define KT     256          // 2*MM prototypes
#define NMAX   131072       // 128*1024 rows
#define TINV   20.0f        // 1/temperature

// ---------------- device scratch (static; no allocation allowed) -----------
__device__ float g_E[(size_t)NMAX * KT];   // exp(sim/T), 128 MB
__device__ float g_pn[KT * DD];            // normalized prototypes
__device__ float g_gated[MM * DD];         // GLU(globalPrototypes) table
__device__ float g_invn[NMAX];             // 1/||x_i||
__device__ float g_cs1[KT], g_cs2[KT], g_cs3[KT];  // column sums per iteration
__device__ int   g_lastIdx[MM];            // last row assigned to each local proto

// packed f32x2 FMA: d.lo += a.lo*b.lo ; d.hi += a.hi*b.hi  (sm_103a FFMA2)
__device__ __forceinline__ void ffma2(unsigned long long& d,
                                      unsigned long long a,
                                      unsigned long long b) {
    asm("fma.rn.f32x2 %0, %1, %2, %0;" : "+l"(d) : "l"(a), "l"(b));
}
__device__ __forceinline__ unsigned long long dup2(float a) {
    unsigned long long r;
    asm("mov.b64 %0, {%1, %1};" : "=l"(r) : "f"(a));
    return r;
}
__device__ __forceinline__ void unpack2(unsigned long long v, float& lo, float& hi) {
    asm("mov.b64 {%0, %1}, %2;" : "=f"(lo), "=f"(hi) : "l"(v));
}
__device__ __forceinline__ unsigned long long pack2(float lo, float hi) {
    unsigned long long r;
    asm("mov.b64 %0, {%1, %2};" : "=l"(r) : "f"(lo), "f"(hi));
    return r;
}

// ---------------- setup: proto normalize + GLU table + resets --------------
__global__ void k_setup(const float* __restrict__ localP,
                        const float* __restrict__ globalP,
                        const float* __restrict__ W,
                        const float* __restrict__ bias) {
    int b = blockIdx.x;
    int t = threadIdx.x;           // 384 threads
    if (b < KT) {
        // L2-normalize prototype row b (local rows 0..127, global 128..255)
        const float* src = (b < MM) ? (localP + b * DD) : (globalP + (b - MM) * DD);
        float v = (t < DD) ? src[t] : 0.0f;
        float ss = v * v;
        #pragma unroll
        for (int o = 16; o; o >>= 1) ss += __shfl_xor_sync(0xffffffffu, ss, o);
        __shared__ float tot;
        if (t == 0) tot = 0.0f;
        __syncthreads();
        if ((t & 31) == 0) atomicAdd(&tot, ss);
        __syncthreads();
        float rinv = rsqrtf(fmaxf(tot, 1e-12f));
        if (t < DD) g_pn[b * DD + t] = v * rinv;
    } else if (b < KT + MM) {
        // GLU table row m: lin = G[m] @ W + b ; gated = lin[:D]*sigmoid(lin[D:])
        int m = b - KT;
        __shared__ float gp[DD];
        __shared__ float lin[2 * DD];
        if (t < DD) gp[t] = globalP[m * DD + t];
        __syncthreads();
        float acc = bias[t];
        for (int k = 0; k < DD; k++) acc += gp[k] * W[k * (2 * DD) + t];
        lin[t] = acc;
        __syncthreads();
        if (t < DD) {
            float z = lin[t + DD];
            float sig = 1.0f / (1.0f + __expf(-z));
            g_gated[m * DD + t] = lin[t] * sig;
        }
    } else {
        // resets (must re-run on every graph replay)
        if (t < KT) { g_cs1[t] = 0.0f; g_cs2[t] = 0.0f; g_cs3[t] = 0.0f; }
        if (t < MM) g_lastIdx[t] = -1;
    }
}

// ---------------- row inverse norms of x -----------------------------------
__global__ void k_rownorm(const float* __restrict__ x, int n) {
    int lane = threadIdx.x & 31;
    int warp = (blockIdx.x * blockDim.x + threadIdx.x) >> 5;
    int nw   = (gridDim.x * blockDim.x) >> 5;
    for (int row = warp; row < n; row += nw) {
        const float* xr = x + (size_t)row * DD;
        float ss = 0.0f;
        #pragma unroll
        for (int k = 0; k < 6; k++) { float v = xr[lane + 32 * k]; ss += v * v; }
        #pragma unroll
        for (int o = 16; o; o >>= 1) ss += __shfl_xor_sync(0xffffffffu, ss, o);
        if (lane == 0) g_invn[row] = rsqrtf(fmaxf(ss, 1e-12f));
    }
}

// ---------------- GEMM: E = exp(sim/T), row factor a1, colsum1 -------------
// C tile 64x256, block 256 threads, each thread owns 4 rows x 16 cols.
// Inner product via packed fma.rn.f32x2 (2 lane-FMAs per issue slot).
#define BR 64
#define KC 32
__global__ __launch_bounds__(256, 2)
void k_gemm(const float* __restrict__ x, int n) {
    __shared__ __align__(16) float xs[KC][BR + 1];      // stride 65
    __shared__ __align__(16) float ps[KC][KT + 4];      // stride 260 (8B-aligned rows)
    __shared__ float red[BR][17];
    __shared__ float a_s[BR];

    int tid = threadIdx.x;
    int tr = tid >> 4;                    // 0..15 row group
    int tc = tid & 15;                    // 0..15 col group
    int r0 = blockIdx.x * BR;

    unsigned long long acc2[4][8];        // packed f32x2 accumulators (4 rows x 16 cols)
    #pragma unroll
    for (int i = 0; i < 4; i++)
        #pragma unroll
        for (int j = 0; j < 8; j++) acc2[i][j] = 0ull;

    for (int k0 = 0; k0 < DD; k0 += KC) {
        #pragma unroll
        for (int it = 0; it < 8; it++) {
            int idx = tid + it * 256;
            int k = idx & 31, r = idx >> 5;
            xs[k][r] = x[(size_t)(r0 + r) * DD + k0 + k];
        }
        #pragma unroll 4
        for (int it = 0; it < 32; it++) {
            int idx = tid + it * 256;
            int k = idx & 31, c = idx >> 5;
            ps[k][c] = g_pn[c * DD + k0 + k];
        }
        __syncthreads();
        #pragma unroll
        for (int kk = 0; kk < KC; kk++) {
            unsigned long long av[4];
            #pragma unroll
            for (int i = 0; i < 4; i++) av[i] = dup2(xs[kk][tr * 4 + i]);
            const unsigned long long* bp =
                (const unsigned long long*)&ps[kk][tc * 16];
            #pragma unroll
            for (int j = 0; j < 8; j++) {
                unsigned long long b = bp[j];
                ffma2(acc2[0][j], av[0], b);
                ffma2(acc2[1][j], av[1], b);
                ffma2(acc2[2][j], av[2], b);
                ffma2(acc2[3][j], av[3], b);
            }
        }
        __syncthreads();
    }

    // epilogue: normalize row, exponentiate, rowsum; store E; repack exps
    float rsum[4] = {0.f, 0.f, 0.f, 0.f};
    float sc[4];
    #pragma unroll
    for (int i = 0; i < 4; i++) sc[i] = g_invn[r0 + tr * 4 + i] * TINV;
    #pragma unroll
    for (int i = 0; i < 4; i++) {
        float2* dst = (float2*)(g_E + (size_t)(r0 + tr * 4 + i) * KT + tc * 16);
        #pragma unroll
        for (int j = 0; j < 8; j++) {
            float lo, hi;
            unpack2(acc2[i][j], lo, hi);
            float e0 = __expf(lo * sc[i]);
            float e1 = __expf(hi * sc[i]);
            rsum[i] += e0 + e1;
            acc2[i][j] = pack2(e0, e1);
            dst[j] = make_float2(e0, e1);
        }
    }

    // a1_i = 1/(n * rowsum_i)
    #pragma unroll
    for (int i = 0; i < 4; i++) red[tr * 4 + i][tc] = rsum[i];
    __syncthreads();
    if (tid < BR) {
        float s = 0.0f;
        #pragma unroll
        for (int j = 0; j < 16; j++) s += red[tid][j];
        a_s[tid] = 1.0f / ((float)n * s);
    }
    __syncthreads();

    // colsum1_j += sum_rows a1_i * E_ij   (block-local reduce, one atomic/col)
    float* cred = &ps[0][0];              // reuse ps smem as [16][256]
    #pragma unroll
    for (int j = 0; j < 8; j++) {
        float s0 = 0.0f, s1 = 0.0f;
        #pragma unroll
        for (int i = 0; i < 4; i++) {
            float lo, hi;
            unpack2(acc2[i][j], lo, hi);
            float a = a_s[tr * 4 + i];
            s0 += a * lo;
            s1 += a * hi;
        }
        cred[tr * 256 + tc * 16 + 2 * j]     = s0;
        cred[tr * 256 + tc * 16 + 2 * j + 1] = s1;
    }
    __syncthreads();
    {
        int c = tid;                      // 256 threads, 256 cols
        float s = 0.0f;
        #pragma unroll
        for (int g = 0; g < 16; g++) s += cred[g * 256 + c];
        atomicAdd(&g_cs1[c], s);
    }
}

// ---------------- sinkhorn pass: b from cs_in; a per-row; accumulate cs_out
template<int P>
__global__ void k_pass(int n) {
    const float* csin  = (P == 1) ? g_cs1 : g_cs2;
    float*       csout = (P == 1) ? g_cs2 : g_cs3;
    int lane = threadIdx.x & 31;
    int warp = (blockIdx.x * blockDim.x + threadIdx.x) >> 5;
    int nw   = (gridDim.x * blockDim.x) >> 5;

    float bb[8];
    #pragma unroll
    for (int j = 0; j < 8; j++) bb[j] = 1.0f / ((float)KT * csin[lane * 8 + j]);

    float cacc[8] = {0.f, 0.f, 0.f, 0.f, 0.f, 0.f, 0.f, 0.f};
    float ninv = 1.0f / (float)n;
    for (int row = warp; row < n; row += nw) {
        const float4* er = (const float4*)(g_E + (size_t)row * KT) + lane * 2;
        float4 e0 = er[0], e1 = er[1];
        float s = e0.x * bb[0] + e0.y * bb[1] + e0.z * bb[2] + e0.w * bb[3]
                + e1.x * bb[4] + e1.y * bb[5] + e1.z * bb[6] + e1.w * bb[7];
        #pragma unroll
        for (int o = 16; o; o >>= 1) s += __shfl_xor_sync(0xffffffffu, s, o);
        float a = ninv / s;
        cacc[0] += a * e0.x; cacc[1] += a * e0.y; cacc[2] += a * e0.z; cacc[3] += a * e0.w;
        cacc[4] += a * e1.x; cacc[5] += a * e1.y; cacc[6] += a * e1.z; cacc[7] += a * e1.w;
    }
    __shared__ float sacc[KT];
    if (threadIdx.x < KT) sacc[threadIdx.x] = 0.0f;
    __syncthreads();
    #pragma unroll
    for (int j = 0; j < 8; j++) atomicAdd(&sacc[lane * 8 + j], cacc[j]);
    __syncthreads();
    if (threadIdx.x < KT) atomicAdd(&csout[threadIdx.x], sacc[threadIdx.x]);
}

// ---------------- final: argmaxes, output blend+normalize, lastIdx ---------
__global__ void k_final(const float* __restrict__ x, float* __restrict__ out, int n) {
    int lane = threadIdx.x & 31;
    int warp = (blockIdx.x * blockDim.x + threadIdx.x) >> 5;
    int nw   = (gridDim.x * blockDim.x) >> 5;

    float bb[8];
    #pragma unroll
    for (int j = 0; j < 8; j++) bb[j] = 1.0f / ((float)KT * g_cs3[lane * 8 + j]);

    for (int row = warp; row < n; row += nw) {
        const float4* er = (const float4*)(g_E + (size_t)row * KT) + lane * 2;
        float4 e0 = er[0], e1 = er[1];
        float v[8] = { e0.x * bb[0], e0.y * bb[1], e0.z * bb[2], e0.w * bb[3],
                       e1.x * bb[4], e1.y * bb[5], e1.z * bb[6], e1.w * bb[7] };
        float best = v[0]; int bi = lane * 8;
        #pragma unroll
        for (int j = 1; j < 8; j++)
            if (v[j] > best) { best = v[j]; bi = lane * 8 + j; }
        // reduce within 16-lane halves (lanes 0..15: local cols, 16..31: global)
        #pragma unroll
        for (int o = 1; o < 16; o <<= 1) {
            float ob = __shfl_xor_sync(0xffffffffu, best, o);
            int  obi = __shfl_xor_sync(0xffffffffu, bi, o);
            if (ob > best || (ob == best && obi < bi)) { best = ob; bi = obi; }
        }
        int lidx = __shfl_sync(0xffffffffu, bi, 0);         // 0..127 (first occurrence)
        int gidx = __shfl_sync(0xffffffffu, bi, 16) - MM;   // 0..127
        if (lane == 0) atomicMax(&g_lastIdx[lidx], row);    // last-write-wins

        const float* xr = x + (size_t)row * DD;
        const float* gt = g_gated + (size_t)gidx * DD;
        float o6[6]; float ss = 0.0f;
        #pragma unroll
        for (int k = 0; k < 6; k++) {
            float ov = 0.5f * (gt[lane + 32 * k] + xr[lane + 32 * k]);
            o6[k] = ov; ss += ov * ov;
        }
        #pragma unroll
        for (int o = 16; o; o >>= 1) ss += __shfl_xor_sync(0xffffffffu, ss, o);
        float rinv = rsqrtf(fmaxf(ss, 1e-12f));
        float* orow = out + (size_t)row * DD;
        #pragma unroll
        for (int k = 0; k < 6; k++) orow[lane + 32 * k] = o6[k] * rinv;
    }
}

// ---------------- EMA finalize: last-write-wins scatter --------------------
__global__ void k_ema(const float* __restrict__ x,
                      const float* __restrict__ localP,
                      float* __restrict__ outLocal) {
    int m = blockIdx.x;
    int t = threadIdx.x;   // 192
    int i = g_lastIdx[m];
    float lv = localP[m * DD + t];
    float v = (i >= 0) ? (0.96f * lv + (1.0f - 0.96f) * x[(size_t)i * DD + t]) : lv;
    outLocal[m * DD + t] = v;
}

// ---------------- launcher -------------------------------------------------
extern "C" void kernel_launch(void* const* d_in, const int* in_sizes, int n_in,
                              void* d_out, int out_size) {
    const float* proj    = (const float*)d_in[0];
    const float* localP  = (const float*)d_in[1];
    const float* globalP = (const float*)d_in[2];
    const float* W       = (const float*)d_in[3];
    const float* bias    = (const float*)d_in[4];
    float* out = (float*)d_out;

    int n = in_sizes[0] / DD;        // 131072
    float* outLocal = out + (size_t)in_sizes[0];

    k_setup<<<KT + MM + 1, 2 * DD>>>(localP, globalP, W, bias);
    k_rownorm<<<512, 256>>>(proj, n);
    k_gemm<<<n / BR, 256>>>(proj, n);
    k_pass<1><<<1024, 256>>>(n);
    k_pass<2><<<1024, 256>>>(n);
    k_final<<<1024, 256>>>(proj, out, n);
    k_ema<<<MM, DD>>>(proj, localP, outLocal);
}

// round 8
// speedup vs baseline: 1.9500x; 1.9500x over previous
#include <cuda_runtime.h>
#include <cstdint>

// Problem constants (fixed shapes for this problem instance)
#define DD     192          // projection dim
#define MM     128          // memory bank size
#define KT     256          // 2*MM prototypes
#define NMAX   131072       // 128*1024 rows
#define TINV   20.0f        // 1/temperature

// ---------------- device scratch (static; no allocation allowed) -----------
__device__ float g_E[(size_t)NMAX * KT];   // exp(sim/T), 128 MB
__device__ float g_pn[KT * DD];            // normalized prototypes
__device__ float g_gated[MM * DD];         // GLU(globalPrototypes) table
__device__ float g_invn[NMAX];             // 1/||x_i||
__device__ float g_cs1[KT], g_cs2[KT], g_cs3[KT];  // column sums per iteration
__device__ int   g_lastIdx[MM];            // last row assigned to each local proto

// packed f32x2 FMA: d.lo += a.lo*b.lo ; d.hi += a.hi*b.hi  (sm_103a FFMA2)
__device__ __forceinline__ void ffma2(unsigned long long& d,
                                      unsigned long long a,
                                      unsigned long long b) {
    asm("fma.rn.f32x2 %0, %1, %2, %0;" : "+l"(d) : "l"(a), "l"(b));
}
__device__ __forceinline__ unsigned long long dup2(float a) {
    unsigned long long r;
    asm("mov.b64 %0, {%1, %1};" : "=l"(r) : "f"(a));
    return r;
}
__device__ __forceinline__ void unpack2(unsigned long long v, float& lo, float& hi) {
    asm("mov.b64 {%0, %1}, %2;" : "=f"(lo), "=f"(hi) : "l"(v));
}
__device__ __forceinline__ unsigned long long pack2(float lo, float hi) {
    unsigned long long r;
    asm("mov.b64 %0, {%1, %2};" : "=l"(r) : "f"(lo), "f"(hi));
    return r;
}

// ---------------- setup: proto normalize + GLU table + resets --------------
__global__ void k_setup(const float* __restrict__ localP,
                        const float* __restrict__ globalP,
                        const float* __restrict__ W,
                        const float* __restrict__ bias) {
    int b = blockIdx.x;
    int t = threadIdx.x;           // 384 threads
    if (b < KT) {
        const float* src = (b < MM) ? (localP + b * DD) : (globalP + (b - MM) * DD);
        float v = (t < DD) ? src[t] : 0.0f;
        float ss = v * v;
        #pragma unroll
        for (int o = 16; o; o >>= 1) ss += __shfl_xor_sync(0xffffffffu, ss, o);
        __shared__ float tot;
        if (t == 0) tot = 0.0f;
        __syncthreads();
        if ((t & 31) == 0) atomicAdd(&tot, ss);
        __syncthreads();
        float rinv = rsqrtf(fmaxf(tot, 1e-12f));
        if (t < DD) g_pn[b * DD + t] = v * rinv;
    } else if (b < KT + MM) {
        // GLU table row m: lin = G[m] @ W + b ; gated = lin[:D]*sigmoid(lin[D:])
        int m = b - KT;
        __shared__ float gp[DD];
        __shared__ float lin[2 * DD];
        if (t < DD) gp[t] = globalP[m * DD + t];
        __syncthreads();
        float acc = bias[t];
        for (int k = 0; k < DD; k++) acc += gp[k] * W[k * (2 * DD) + t];
        lin[t] = acc;
        __syncthreads();
        if (t < DD) {
            float z = lin[t + DD];
            float sig = 1.0f / (1.0f + __expf(-z));
            g_gated[m * DD + t] = lin[t] * sig;
        }
    } else {
        // resets (must re-run on every graph replay)
        if (t < KT) { g_cs1[t] = 0.0f; g_cs2[t] = 0.0f; g_cs3[t] = 0.0f; }
        if (t < MM) g_lastIdx[t] = -1;
    }
}

// ---------------- row inverse norms of x -----------------------------------
__global__ void k_rownorm(const float* __restrict__ x, int n) {
    int lane = threadIdx.x & 31;
    int warp = (blockIdx.x * blockDim.x + threadIdx.x) >> 5;
    int nw   = (gridDim.x * blockDim.x) >> 5;
    for (int row = warp; row < n; row += nw) {
        const float* xr = x + (size_t)row * DD;
        float ss = 0.0f;
        #pragma unroll
        for (int k = 0; k < 6; k++) { float v = xr[lane + 32 * k]; ss += v * v; }
        #pragma unroll
        for (int o = 16; o; o >>= 1) ss += __shfl_xor_sync(0xffffffffu, ss, o);
        if (lane == 0) g_invn[row] = rsqrtf(fmaxf(ss, 1e-12f));
    }
}

// ---------------- GEMM: E = exp(sim/T), row factor a1, colsum1 -------------
// C tile 64x256, block 256 threads, each thread owns 4 rows x 16 cols.
// fma.rn.f32x2 inner product; B tile bank-swizzled: column c stored at
// c + 2*(c>>4) so the 16 tc-segment bases (72 B apart) cover all 16
// bank-pair offsets mod 128 -> conflict-free LDS.64 in the hot loop.
#define BR 64
#define KC 32
#define PSS 290                 // ps row stride (floats); 290*4 mod 128 = 8
__global__ __launch_bounds__(256, 2)
void k_gemm(const float* __restrict__ x, int n) {
    __shared__ __align__(16) float xs[KC][BR + 1];      // stride 65: full bank cycle
    __shared__ __align__(16) float ps[KC][PSS];
    __shared__ float red[BR][17];
    __shared__ float a_s[BR];

    int tid = threadIdx.x;
    int tr = tid >> 4;                    // 0..15 row group
    int tc = tid & 15;                    // 0..15 col group
    int r0 = blockIdx.x * BR;

    unsigned long long acc2[4][8];        // packed f32x2 accumulators
    #pragma unroll
    for (int i = 0; i < 4; i++)
        #pragma unroll
        for (int j = 0; j < 8; j++) acc2[i][j] = 0ull;

    for (int k0 = 0; k0 < DD; k0 += KC) {
        #pragma unroll
        for (int it = 0; it < 8; it++) {
            int idx = tid + it * 256;
            int k = idx & 31, r = idx >> 5;
            xs[k][r] = x[(size_t)(r0 + r) * DD + k0 + k];
        }
        #pragma unroll 4
        for (int it = 0; it < 32; it++) {
            int idx = tid + it * 256;
            int k = idx & 31, c = idx >> 5;
            ps[k][c + ((c >> 4) << 1)] = g_pn[c * DD + k0 + k];   // swizzled store
        }
        __syncthreads();
        #pragma unroll
        for (int kk = 0; kk < KC; kk++) {
            unsigned long long av[4];
            #pragma unroll
            for (int i = 0; i < 4; i++) av[i] = dup2(xs[kk][tr * 4 + i]);
            const unsigned long long* bp =
                (const unsigned long long*)&ps[kk][tc * 18];      // swizzled base
            #pragma unroll
            for (int j = 0; j < 8; j++) {
                unsigned long long b = bp[j];
                ffma2(acc2[0][j], av[0], b);
                ffma2(acc2[1][j], av[1], b);
                ffma2(acc2[2][j], av[2], b);
                ffma2(acc2[3][j], av[3], b);
            }
        }
        __syncthreads();
    }

    // epilogue: normalize row, exponentiate, rowsum; store E; repack exps
    float rsum[4] = {0.f, 0.f, 0.f, 0.f};
    float sc[4];
    #pragma unroll
    for (int i = 0; i < 4; i++) sc[i] = g_invn[r0 + tr * 4 + i] * TINV;
    #pragma unroll
    for (int i = 0; i < 4; i++) {
        float2* dst = (float2*)(g_E + (size_t)(r0 + tr * 4 + i) * KT + tc * 16);
        #pragma unroll
        for (int j = 0; j < 8; j++) {
            float lo, hi;
            unpack2(acc2[i][j], lo, hi);
            float e0 = __expf(lo * sc[i]);
            float e1 = __expf(hi * sc[i]);
            rsum[i] += e0 + e1;
            acc2[i][j] = pack2(e0, e1);
            dst[j] = make_float2(e0, e1);
        }
    }

    // a1_i = 1/(n * rowsum_i)
    #pragma unroll
    for (int i = 0; i < 4; i++) red[tr * 4 + i][tc] = rsum[i];
    __syncthreads();
    if (tid < BR) {
        float s = 0.0f;
        #pragma unroll
        for (int j = 0; j < 16; j++) s += red[tid][j];
        a_s[tid] = 1.0f / ((float)n * s);
    }
    __syncthreads();

    // colsum1_j += sum_rows a1_i * E_ij   (block-local reduce, one atomic/col)
    float* cred = &ps[0][0];              // reuse ps smem as [16][256]
    #pragma unroll
    for (int j = 0; j < 8; j++) {
        float s0 = 0.0f, s1 = 0.0f;
        #pragma unroll
        for (int i = 0; i < 4; i++) {
            float lo, hi;
            unpack2(acc2[i][j], lo, hi);
            float a = a_s[tr * 4 + i];
            s0 += a * lo;
            s1 += a * hi;
        }
        cred[tr * 256 + tc * 16 + 2 * j]     = s0;
        cred[tr * 256 + tc * 16 + 2 * j + 1] = s1;
    }
    __syncthreads();
    {
        int c = tid;                      // 256 threads, 256 cols
        float s = 0.0f;
        #pragma unroll
        for (int g = 0; g < 16; g++) s += cred[g * 256 + c];
        atomicAdd(&g_cs1[c], s);
    }
}

// ---------------- sinkhorn pass: b from cs_in; a per-row; accumulate cs_out
// 4 rows per warp iteration: 8 LDG.128 in flight before the reduce chains.
template<int P>
__global__ void k_pass(int n) {
    const float* csin  = (P == 1) ? g_cs1 : g_cs2;
    float*       csout = (P == 1) ? g_cs2 : g_cs3;
    int lane = threadIdx.x & 31;
    int warp = (blockIdx.x * blockDim.x + threadIdx.x) >> 5;
    int nw   = (gridDim.x * blockDim.x) >> 5;

    float bb[8];
    #pragma unroll
    for (int j = 0; j < 8; j++) bb[j] = 1.0f / ((float)KT * csin[lane * 8 + j]);

    float cacc[8] = {0.f, 0.f, 0.f, 0.f, 0.f, 0.f, 0.f, 0.f};
    float ninv = 1.0f / (float)n;
    for (int rg = warp * 4; rg < n; rg += nw * 4) {
        float4 e[4][2];
        #pragma unroll
        for (int r = 0; r < 4; r++) {
            const float4* er = (const float4*)(g_E + (size_t)(rg + r) * KT) + lane * 2;
            e[r][0] = er[0]; e[r][1] = er[1];
        }
        #pragma unroll
        for (int r = 0; r < 4; r++) {
            float s = e[r][0].x * bb[0] + e[r][0].y * bb[1] + e[r][0].z * bb[2] + e[r][0].w * bb[3]
                    + e[r][1].x * bb[4] + e[r][1].y * bb[5] + e[r][1].z * bb[6] + e[r][1].w * bb[7];
            #pragma unroll
            for (int o = 16; o; o >>= 1) s += __shfl_xor_sync(0xffffffffu, s, o);
            float a = ninv / s;
            cacc[0] += a * e[r][0].x; cacc[1] += a * e[r][0].y;
            cacc[2] += a * e[r][0].z; cacc[3] += a * e[r][0].w;
            cacc[4] += a * e[r][1].x; cacc[5] += a * e[r][1].y;
            cacc[6] += a * e[r][1].z; cacc[7] += a * e[r][1].w;
        }
    }
    __shared__ float sacc[KT];
    if (threadIdx.x < KT) sacc[threadIdx.x] = 0.0f;
    __syncthreads();
    #pragma unroll
    for (int j = 0; j < 8; j++) atomicAdd(&sacc[lane * 8 + j], cacc[j]);
    __syncthreads();
    if (threadIdx.x < KT) atomicAdd(&csout[threadIdx.x], sacc[threadIdx.x]);
}

// ---------------- final: argmaxes, output blend+normalize, lastIdx ---------
__global__ void k_final(const float* __restrict__ x, float* __restrict__ out, int n) {
    int lane = threadIdx.x & 31;
    int warp = (blockIdx.x * blockDim.x + threadIdx.x) >> 5;
    int nw   = (gridDim.x * blockDim.x) >> 5;

    float bb[8];
    #pragma unroll
    for (int j = 0; j < 8; j++) bb[j] = 1.0f / ((float)KT * g_cs3[lane * 8 + j]);

    for (int rg = warp * 2; rg < n; rg += nw * 2) {
        float4 e[2][2];
        #pragma unroll
        for (int r = 0; r < 2; r++) {
            const float4* er = (const float4*)(g_E + (size_t)(rg + r) * KT) + lane * 2;
            e[r][0] = er[0]; e[r][1] = er[1];
        }
        #pragma unroll
        for (int r = 0; r < 2; r++) {
            int row = rg + r;
            float v[8] = { e[r][0].x * bb[0], e[r][0].y * bb[1], e[r][0].z * bb[2], e[r][0].w * bb[3],
                           e[r][1].x * bb[4], e[r][1].y * bb[5], e[r][1].z * bb[6], e[r][1].w * bb[7] };
            float best = v[0]; int bi = lane * 8;
            #pragma unroll
            for (int j = 1; j < 8; j++)
                if (v[j] > best) { best = v[j]; bi = lane * 8 + j; }
            // reduce within 16-lane halves (lanes 0..15: local cols, 16..31: global)
            #pragma unroll
            for (int o = 1; o < 16; o <<= 1) {
                float ob = __shfl_xor_sync(0xffffffffu, best, o);
                int  obi = __shfl_xor_sync(0xffffffffu, bi, o);
                if (ob > best || (ob == best && obi < bi)) { best = ob; bi = obi; }
            }
            int lidx = __shfl_sync(0xffffffffu, bi, 0);         // 0..127 (first occurrence)
            int gidx = __shfl_sync(0xffffffffu, bi, 16) - MM;   // 0..127
            if (lane == 0) atomicMax(&g_lastIdx[lidx], row);    // last-write-wins

            const float* xr = x + (size_t)row * DD;
            const float* gt = g_gated + (size_t)gidx * DD;
            float o6[6]; float ss = 0.0f;
            #pragma unroll
            for (int k = 0; k < 6; k++) {
                float ov = 0.5f * (gt[lane + 32 * k] + xr[lane + 32 * k]);
                o6[k] = ov; ss += ov * ov;
            }
            #pragma unroll
            for (int o = 16; o; o >>= 1) ss += __shfl_xor_sync(0xffffffffu, ss, o);
            float rinv = rsqrtf(fmaxf(ss, 1e-12f));
            float* orow = out + (size_t)row * DD;
            #pragma unroll
            for (int k = 0; k < 6; k++) orow[lane + 32 * k] = o6[k] * rinv;
        }
    }
}

// ---------------- EMA finalize: last-write-wins scatter --------------------
__global__ void k_ema(const float* __restrict__ x,
                      const float* __restrict__ localP,
                      float* __restrict__ outLocal) {
    int m = blockIdx.x;
    int t = threadIdx.x;   // 192
    int i = g_lastIdx[m];
    float lv = localP[m * DD + t];
    float v = (i >= 0) ? (0.96f * lv + (1.0f - 0.96f) * x[(size_t)i * DD + t]) : lv;
    outLocal[m * DD + t] = v;
}

// ---------------- launcher -------------------------------------------------
extern "C" void kernel_launch(void* const* d_in, const int* in_sizes, int n_in,
                              void* d_out, int out_size) {
    const float* proj    = (const float*)d_in[0];
    const float* localP  = (const float*)d_in[1];
    const float* globalP = (const float*)d_in[2];
    const float* W       = (const float*)d_in[3];
    const float* bias    = (const float*)d_in[4];
    float* out = (float*)d_out;

    int n = in_sizes[0] / DD;        // 131072
    float* outLocal = out + (size_t)in_sizes[0];

    k_setup<<<KT + MM + 1, 2 * DD>>>(localP, globalP, W, bias);
    k_rownorm<<<512, 256>>>(proj, n);
    k_gemm<<<n / BR, 256>>>(proj, n);
    k_pass<1><<<1024, 256>>>(n);
    k_pass<2><<<1024, 256>>>(n);
    k_final<<<1024, 256>>>(proj, out, n);
    k_ema<<<MM, DD>>>(proj, localP, outLocal);
}